// round 5
// baseline (speedup 1.0000x reference)
#include <cuda_runtime.h>
#include <cuda_bf16.h>
#include <math.h>
#include <stdint.h>

#define TT 4096
#define KTOT (64*4096)   /* 262144 */
#define FD 512

// ---------------- scratch (static device globals) ----------------
__device__ __nv_bfloat16 g_Ah[(size_t)320 * KTOT];
__device__ __nv_bfloat16 g_Al[(size_t)320 * KTOT];
__device__ __nv_bfloat16 g_Wh[(size_t)KTOT * FD];
__device__ __nv_bfloat16 g_Wl[(size_t)KTOT * FD];
__device__ float g_feats[320 * FD];
__device__ float g_norms[320];
__device__ float g_cons;
__device__ float g_contr;

// ---------------- PTX helpers (baseline ISA only) ----------------
__device__ __forceinline__ uint32_t smem_to_u32(const void* p) {
    uint32_t a;
    asm("{ .reg .u64 t; cvta.to.shared.u64 t, %1; cvt.u32.u64 %0, t; }" : "=r"(a) : "l"(p));
    return a;
}
__device__ __forceinline__ void ldsm_x4(uint32_t* r, uint32_t addr) {
    asm volatile("ldmatrix.sync.aligned.m8n8.x4.shared.b16 {%0,%1,%2,%3}, [%4];"
        : "=r"(r[0]), "=r"(r[1]), "=r"(r[2]), "=r"(r[3]) : "r"(addr));
}
__device__ __forceinline__ void ldsm_x2_trans(uint32_t* r, uint32_t addr) {
    asm volatile("ldmatrix.sync.aligned.m8n8.x2.trans.shared.b16 {%0,%1}, [%2];"
        : "=r"(r[0]), "=r"(r[1]) : "r"(addr));
}
__device__ __forceinline__ void mma_bf16(float* c, const uint32_t* a, const uint32_t* b) {
    asm volatile("mma.sync.aligned.m16n8k16.row.col.f32.bf16.bf16.f32 "
        "{%0,%1,%2,%3}, {%4,%5,%6,%7}, {%8,%9}, {%0,%1,%2,%3};"
        : "+f"(c[0]), "+f"(c[1]), "+f"(c[2]), "+f"(c[3])
        : "r"(a[0]), "r"(a[1]), "r"(a[2]), "r"(a[3]), "r"(b[0]), "r"(b[1]));
}
__device__ __forceinline__ void cp_async16(uint32_t smem, const void* g) {
    asm volatile("cp.async.cg.shared.global [%0], [%1], 16;" :: "r"(smem), "l"(g));
}
#define CP_COMMIT() asm volatile("cp.async.commit_group;" ::: "memory")
#define CP_WAIT1()  asm volatile("cp.async.wait_group 1;" ::: "memory")
#define CP_WAIT0()  asm volatile("cp.async.wait_group 0;" ::: "memory")

// ---------------- block reductions ----------------
__device__ __forceinline__ float blockReduceSum(float v, float* red) {
    int lane = threadIdx.x & 31, w = threadIdx.x >> 5;
    int nw = blockDim.x >> 5;
    #pragma unroll
    for (int o = 16; o; o >>= 1) v += __shfl_down_sync(0xffffffffu, v, o);
    if (lane == 0) red[w] = v;
    __syncthreads();
    if (w == 0) {
        float r = (lane < nw) ? red[lane] : 0.0f;
        #pragma unroll
        for (int o = 8; o; o >>= 1) r += __shfl_down_sync(0xffffffffu, r, o);
        if (lane == 0) red[0] = r;
    }
    __syncthreads();
    float out = red[0];
    __syncthreads();
    return out;
}
__device__ __forceinline__ float blockReduceMax(float v, float* red) {
    int lane = threadIdx.x & 31, w = threadIdx.x >> 5;
    int nw = blockDim.x >> 5;
    #pragma unroll
    for (int o = 16; o; o >>= 1) v = fmaxf(v, __shfl_down_sync(0xffffffffu, v, o));
    if (lane == 0) red[w] = v;
    __syncthreads();
    if (w == 0) {
        float r = (lane < nw) ? red[lane] : -3.4e38f;
        #pragma unroll
        for (int o = 8; o; o >>= 1) r = fmaxf(r, __shfl_down_sync(0xffffffffu, r, o));
        if (lane == 0) red[0] = r;
    }
    __syncthreads();
    float out = red[0];
    __syncthreads();
    return out;
}

// ---------------- masks ----------------
template<int MID>
__device__ __forceinline__ float maskval(int k, int fs) {
    float fm = (k >= fs && k < fs + 409) ? 0.1f : 1.0f;
    if (MID == 0) return (k < 2048) ? 1.0f : 0.0f;
    if (MID == 1) return fm;
    float g = (k == 0) ? 1.0f : ((k <= 1024) ? 0.5f : ((k < 3072) ? 1.0f : 0.5f));
    return g * fm;
}

// skewed smem index for FFT planes (reduces scatter-write bank conflicts)
__device__ __forceinline__ int skw(int g) { return g + (g >> 4); }
#define PLANE 4352   /* floats per skewed 4096-plane */

// ---------------- kernel 0: init ----------------
__global__ void init_kernel(const float* __restrict__ b) {
    int i = blockIdx.x * blockDim.x + threadIdx.x;
    if (i < 320 * FD) g_feats[i] = b[i & 511];
    if (i == 0) { g_cons = 0.0f; g_contr = 0.0f; }
}

// ---------------- kernel 1: fused views (FFT) + W split ----------------
// grid 4608: block bx with bx%9==0 does a W-split slice; others do one FFT row.
__device__ __forceinline__ void store_hl(size_t idx, float v) {
    __nv_bfloat16 h = __float2bfloat16_rn(v);
    g_Ah[idx] = h;
    g_Al[idx] = __float2bfloat16_rn(v - __bfloat162float(h));
}

__global__ void __launch_bounds__(512, 1)
views_kernel(const float* __restrict__ x, const float* __restrict__ W,
             const float* __restrict__ nz1, const float* __restrict__ nz2,
             const int* __restrict__ pfs, const int* __restrict__ pts) {
    const int bx = blockIdx.x;
    const int grp = bx / 9, rr9 = bx % 9;
    const int tid = threadIdx.x;

    if (rr9 == 0) {
        // ---- W hi/lo split slice (streams 1MB fp32 -> 1MB bf16 planes) ----
        size_t base = (size_t)grp * 262144;
        #pragma unroll 1
        for (int j = 0; j < 64; j++) {
            size_t i = base + (size_t)j * 4096 + (size_t)tid * 8;
            float4 v0 = *(const float4*)(W + i);
            float4 v1 = *(const float4*)(W + i + 4);
            __align__(16) __nv_bfloat16 hi[8], lo[8];
            float vv[8] = {v0.x, v0.y, v0.z, v0.w, v1.x, v1.y, v1.z, v1.w};
            #pragma unroll
            for (int q = 0; q < 8; q++) {
                __nv_bfloat16 h = __float2bfloat16_rn(vv[q]);
                hi[q] = h;
                lo[q] = __float2bfloat16_rn(vv[q] - __bfloat162float(h));
            }
            *(float4*)(g_Wh + i) = *(float4*)hi;
            *(float4*)(g_Wl + i) = *(float4*)lo;
        }
        return;
    }

    // ---- FFT views block ----
    extern __shared__ char smraw[];
    float2* tw = (float2*)smraw;                    // 3072 float2 = 24576 B
    float* P = (float*)(smraw + 24576);             // 6 planes of PLANE floats
    float* Ar = P;               float* Ai = Ar + PLANE;
    float* Br = Ai + PLANE;      float* Bi = Br + PLANE;
    float* Cr = Bi + PLANE;      float* Ci = Cr + PLANE;
    __shared__ float red[32];

    const int row = grp * 8 + (rr9 - 1);           // 0..4095
    const int bi = row >> 6, ci = row & 63;
    const int fs = *pfs, ts = *pts;
    const size_t xbase = (size_t)row * TT;

    const size_t a0 = (size_t)(0*64 + bi) * KTOT + (size_t)ci * TT;
    const size_t a1 = (size_t)(1*64 + bi) * KTOT + (size_t)ci * TT;
    const size_t a2 = (size_t)(2*64 + bi) * KTOT + (size_t)ci * TT;
    const size_t a3 = (size_t)(3*64 + bi) * KTOT + (size_t)ci * TT;
    const size_t a4 = (size_t)(4*64 + bi) * KTOT + (size_t)ci * TT;

    for (int k = tid; k < 3072; k += 512) {
        float s, c;
        sincospif(-(float)k * (1.0f / 2048.0f), &s, &c);
        tw[k] = make_float2(c, s);
    }

    float ls = 0.0f, lq = 0.0f;
    for (int t = tid; t < TT; t += 512) {
        float v = x[xbase + t];
        Ar[skw(t)] = v; Ai[skw(t)] = 0.0f;
        store_hl(a0 + t, v);
        ls += v; lq += v * v;
    }
    float s1 = blockReduceSum(ls, red);
    float q1 = blockReduceSum(lq, red);
    float std1 = sqrtf(fmaxf(0.0f, (q1 - s1 * s1 * (1.0f / 4096.0f)) * (1.0f / 4095.0f)));

    for (int t = tid; t < TT; t += 512)
        store_hl(a3 + t, x[xbase + t] + nz1[xbase + t] * (0.02f * std1));

    // ---- forward radix-4 Stockham (6 stages, A<->B, result in A) ----
    {
        float *srr = Ar, *sri = Ai, *drr = Br, *dri = Bi;
        #pragma unroll 1
        for (int s2 = 0; s2 < 12; s2 += 2) {
            const int m = 1 << s2;
            __syncthreads();
            #pragma unroll
            for (int i = tid; i < 1024; i += 512) {
                int jm = (i >> s2) << s2;
                float e0r = srr[skw(i)],        e0i = sri[skw(i)];
                float e1r = srr[skw(i + 1024)], e1i = sri[skw(i + 1024)];
                float e2r = srr[skw(i + 2048)], e2i = sri[skw(i + 2048)];
                float e3r = srr[skw(i + 3072)], e3i = sri[skw(i + 3072)];
                float s02r = e0r + e2r, s02i = e0i + e2i;
                float d02r = e0r - e2r, d02i = e0i - e2i;
                float s13r = e1r + e3r, s13i = e1i + e3i;
                float d13r = e1r - e3r, d13i = e1i - e3i;
                int base = i + 3 * jm;
                drr[skw(base)] = s02r + s13r; dri[skw(base)] = s02i + s13i;
                float2 w1 = tw[jm], w2 = tw[2 * jm], w3 = tw[3 * jm];
                float y1r = d02r + d13i, y1i = d02i - d13r;
                drr[skw(base + m)]   = w1.x * y1r - w1.y * y1i;
                dri[skw(base + m)]   = w1.x * y1i + w1.y * y1r;
                float y2r = s02r - s13r, y2i = s02i - s13i;
                drr[skw(base + 2*m)] = w2.x * y2r - w2.y * y2i;
                dri[skw(base + 2*m)] = w2.x * y2i + w2.y * y2r;
                float y3r = d02r - d13i, y3i = d02i + d13r;
                drr[skw(base + 3*m)] = w3.x * y3r - w3.y * y3i;
                dri[skw(base + 3*m)] = w3.x * y3i + w3.y * y3r;
            }
            float* t;
            t = srr; srr = drr; drr = t;
            t = sri; sri = dri; dri = t;
        }
        __syncthreads();
    }
    // X now in Ar/Ai (preserved across the 3 masked inverse passes)

    // ---- three masked inverse passes ----
    #pragma unroll 1
    for (int pass = 0; pass < 3; pass++) {
        // stage 0 (m=1): read X with mask, conj twiddles, write B
        __syncthreads();
        #pragma unroll
        for (int i = tid; i < 1024; i += 512) {
            float m0, m1, m2, m3;
            if (pass == 0) {
                m0 = maskval<0>(i, fs); m1 = maskval<0>(i + 1024, fs);
                m2 = maskval<0>(i + 2048, fs); m3 = maskval<0>(i + 3072, fs);
            } else if (pass == 1) {
                m0 = maskval<1>(i, fs); m1 = maskval<1>(i + 1024, fs);
                m2 = maskval<1>(i + 2048, fs); m3 = maskval<1>(i + 3072, fs);
            } else {
                m0 = maskval<2>(i, fs); m1 = maskval<2>(i + 1024, fs);
                m2 = maskval<2>(i + 2048, fs); m3 = maskval<2>(i + 3072, fs);
            }
            float e0r = Ar[skw(i)] * m0,        e0i = Ai[skw(i)] * m0;
            float e1r = Ar[skw(i + 1024)] * m1, e1i = Ai[skw(i + 1024)] * m1;
            float e2r = Ar[skw(i + 2048)] * m2, e2i = Ai[skw(i + 2048)] * m2;
            float e3r = Ar[skw(i + 3072)] * m3, e3i = Ai[skw(i + 3072)] * m3;
            float s02r = e0r + e2r, s02i = e0i + e2i;
            float d02r = e0r - e2r, d02i = e0i - e2i;
            float s13r = e1r + e3r, s13i = e1i + e3i;
            float d13r = e1r - e3r, d13i = e1i - e3i;
            int base = 4 * i;
            Br[skw(base)] = s02r + s13r; Bi[skw(base)] = s02i + s13i;
            float2 w1 = tw[i], w2 = tw[2 * i], w3 = tw[3 * i];
            // cmulc(w, y) = (w.x*y.r + w.y*y.i, w.x*y.i - w.y*y.r)
            float y1r = d02r - d13i, y1i = d02i + d13r;
            Br[skw(base + 1)] = w1.x * y1r + w1.y * y1i;
            Bi[skw(base + 1)] = w1.x * y1i - w1.y * y1r;
            float y2r = s02r - s13r, y2i = s02i - s13i;
            Br[skw(base + 2)] = w2.x * y2r + w2.y * y2i;
            Bi[skw(base + 2)] = w2.x * y2i - w2.y * y2r;
            float y3r = d02r + d13i, y3i = d02i - d13r;
            Br[skw(base + 3)] = w3.x * y3r + w3.y * y3i;
            Bi[skw(base + 3)] = w3.x * y3i - w3.y * y3r;
        }
        // 5 more stages: B <-> C, result lands in C
        {
            float *srr = Br, *sri = Bi, *drr = Cr, *dri = Ci;
            #pragma unroll 1
            for (int s2 = 2; s2 < 12; s2 += 2) {
                const int m = 1 << s2;
                __syncthreads();
                #pragma unroll
                for (int i = tid; i < 1024; i += 512) {
                    int jm = (i >> s2) << s2;
                    float e0r = srr[skw(i)],        e0i = sri[skw(i)];
                    float e1r = srr[skw(i + 1024)], e1i = sri[skw(i + 1024)];
                    float e2r = srr[skw(i + 2048)], e2i = sri[skw(i + 2048)];
                    float e3r = srr[skw(i + 3072)], e3i = sri[skw(i + 3072)];
                    float s02r = e0r + e2r, s02i = e0i + e2i;
                    float d02r = e0r - e2r, d02i = e0i - e2i;
                    float s13r = e1r + e3r, s13i = e1i + e3i;
                    float d13r = e1r - e3r, d13i = e1i - e3i;
                    int base = i + 3 * jm;
                    drr[skw(base)] = s02r + s13r; dri[skw(base)] = s02i + s13i;
                    float2 w1 = tw[jm], w2 = tw[2 * jm], w3 = tw[3 * jm];
                    float y1r = d02r - d13i, y1i = d02i + d13r;
                    drr[skw(base + m)]   = w1.x * y1r + w1.y * y1i;
                    dri[skw(base + m)]   = w1.x * y1i - w1.y * y1r;
                    float y2r = s02r - s13r, y2i = s02i - s13i;
                    drr[skw(base + 2*m)] = w2.x * y2r + w2.y * y2i;
                    dri[skw(base + 2*m)] = w2.x * y2i - w2.y * y2r;
                    float y3r = d02r + d13i, y3i = d02i - d13r;
                    drr[skw(base + 3*m)] = w3.x * y3r + w3.y * y3i;
                    dri[skw(base + 3*m)] = w3.x * y3i - w3.y * y3r;
                }
                float* t;
                t = srr; srr = drr; drr = t;
                t = sri; sri = dri; dri = t;
            }
            __syncthreads();
        }
        // consume result (in Cr)
        if (pass == 0) {
            for (int t = tid; t < TT; t += 512)
                store_hl(a1 + t, Cr[skw(t)] * (1.0f / 4096.0f));
        } else if (pass == 1) {
            for (int t = tid; t < TT; t += 512) {
                float tm = (t >= ts && t < ts + 204) ? 0.1f : 1.0f;
                store_hl(a2 + t, tm * Cr[skw(t)] * (1.0f / 4096.0f));
            }
        } else {
            float ls2 = 0.0f, lq2 = 0.0f;
            for (int t = tid; t < TT; t += 512) {
                float tm = (t >= ts && t < ts + 204) ? 0.1f : 1.0f;
                float v = tm * Cr[skw(t)] * (1.0f / 4096.0f);
                ls2 += v; lq2 += v * v;
            }
            float s2 = blockReduceSum(ls2, red);
            float q2 = blockReduceSum(lq2, red);
            float std2 = sqrtf(fmaxf(0.0f, (q2 - s2 * s2 * (1.0f / 4096.0f)) * (1.0f / 4095.0f)));
            for (int t = tid; t < TT; t += 512) {
                float tm = (t >= ts && t < ts + 204) ? 0.1f : 1.0f;
                float v = tm * Cr[skw(t)] * (1.0f / 4096.0f);
                store_hl(a4 + t, v + nz2[xbase + t] * (0.02f * std2));
            }
        }
    }
}

// ---------------- kernel 2: 3-stage async mma.sync bf16-split GEMM ----------------
// stage layout (24576 B): AH[0,4K) AL[4K,8K) WH[8K,16K) WL[16K,24K)
#define STG 24576
#define GEMM_SMEM (3 * STG)   /* 73728 */

__global__ void __launch_bounds__(128, 3) gemm_kernel() {
    extern __shared__ char smbuf[];
    const uint32_t sb = smem_to_u32(smbuf);

    const int tid = threadIdx.x;
    const int warp = tid >> 5, lane = tid & 31;
    const int m0 = blockIdx.y * 64;
    const int n0 = blockIdx.x * 128;
    const int z = blockIdx.z;
    const int start_chunk = 372 * z + (z < 8 ? z : 8);
    const int nchunks = 372 + (z < 8 ? 1 : 0);

    const int wm = warp >> 1;
    const int wn = warp & 1;

    float acc[2][8][4];
    #pragma unroll
    for (int a = 0; a < 2; a++)
        #pragma unroll
        for (int b = 0; b < 8; b++)
            #pragma unroll
            for (int c = 0; c < 4; c++) acc[a][b][c] = 0.0f;

    // cp.async sources + dst offsets
    const __nv_bfloat16* srcA[4];
    uint32_t dstA[4];
    #pragma unroll
    for (int i = 0; i < 2; i++) {
        int f = tid + 128 * i;
        int m = f >> 2, kc = f & 3;
        uint32_t rel = (uint32_t)(m * 64 + (((kc + (m >> 1)) & 3) << 4));
        size_t src = (size_t)(m0 + m) * KTOT + (size_t)start_chunk * 32 + kc * 8;
        dstA[i] = rel;            srcA[i] = g_Ah + src;
        dstA[i + 2] = rel + 4096; srcA[i + 2] = g_Al + src;
    }
    const __nv_bfloat16* srcW[8];
    uint32_t dstW[8];
    #pragma unroll
    for (int i = 0; i < 4; i++) {
        int f = tid + 128 * i;
        int k = f >> 4, nc = f & 15;
        uint32_t rel = (uint32_t)(8192 + k * 256 + (((nc ^ (k & 7)) & 15) << 4));
        size_t src = ((size_t)start_chunk * 32 + k) * 512 + n0 + nc * 8;
        dstW[i] = rel;            srcW[i] = g_Wh + src;
        dstW[i + 4] = rel + 8192; srcW[i + 4] = g_Wl + src;
    }

    // ldmatrix addresses (stage-relative)
    uint32_t a_ld[2][2];
    {
        int tile = lane >> 3, r = lane & 7;
        #pragma unroll
        for (int mt = 0; mt < 2; mt++)
            #pragma unroll
            for (int kt = 0; kt < 2; kt++) {
                int mm = wm * 32 + mt * 16 + (tile & 1) * 8 + r;
                int kb = kt * 2 + (tile >> 1);
                a_ld[mt][kt] = (uint32_t)(mm * 64 + (((kb + (mm >> 1)) & 3) << 4));
            }
    }
    uint32_t b_ld[8][2];
    {
        int lr = lane & 15;
        #pragma unroll
        for (int nt = 0; nt < 8; nt++) {
            int nb = wn * 8 + nt;
            #pragma unroll
            for (int kt = 0; kt < 2; kt++) {
                int k = kt * 16 + lr;
                b_ld[nt][kt] = (uint32_t)(8192 + k * 256 + (((nb ^ (k & 7)) & 15) << 4));
            }
        }
    }

    auto issue = [&](uint32_t sbase) {
        #pragma unroll
        for (int i = 0; i < 4; i++) {
            cp_async16(sb + sbase + dstA[i], srcA[i]);
            srcA[i] += 32;
        }
        #pragma unroll
        for (int i = 0; i < 8; i++) {
            cp_async16(sb + sbase + dstW[i], srcW[i]);
            srcW[i] += 32 * 512;
        }
    };

    issue(0);       CP_COMMIT();
    issue(STG);     CP_COMMIT();

    int cur = 0, nxt2 = 2 * STG;
    for (int it = 0; it < nchunks; ++it) {
        if (it + 1 < nchunks) { CP_WAIT1(); } else { CP_WAIT0(); }
        __syncthreads();
        if (it + 2 < nchunks) {
            issue((uint32_t)nxt2);
            CP_COMMIT();
            nxt2 += STG; if (nxt2 == 3 * STG) nxt2 = 0;
        }
        const uint32_t cbase = (uint32_t)cur;
        cur += STG; if (cur == 3 * STG) cur = 0;

        #pragma unroll
        for (int kt = 0; kt < 2; kt++) {
            uint32_t ah[2][4], al[2][4];
            #pragma unroll
            for (int mt = 0; mt < 2; mt++) {
                ldsm_x4(ah[mt], sb + cbase + a_ld[mt][kt]);
                ldsm_x4(al[mt], sb + cbase + a_ld[mt][kt] + 4096);
            }
            uint32_t bh[8][2], bl[8][2];
            #pragma unroll
            for (int nt = 0; nt < 8; nt++) {
                ldsm_x2_trans(bh[nt], sb + cbase + b_ld[nt][kt]);
                ldsm_x2_trans(bl[nt], sb + cbase + b_ld[nt][kt] + 8192);
            }
            #pragma unroll
            for (int mt = 0; mt < 2; mt++)
                #pragma unroll
                for (int nt = 0; nt < 8; nt++) {
                    mma_bf16(acc[mt][nt], ah[mt], bh[nt]);
                    mma_bf16(acc[mt][nt], ah[mt], bl[nt]);
                    mma_bf16(acc[mt][nt], al[mt], bh[nt]);
                }
        }
    }

    // epilogue
    {
        const int g = lane >> 2, t4 = lane & 3;
        #pragma unroll
        for (int mt = 0; mt < 2; mt++) {
            int r0 = m0 + wm * 32 + mt * 16 + g;
            int r1 = r0 + 8;
            #pragma unroll
            for (int nt = 0; nt < 8; nt++) {
                int col = n0 + wn * 64 + nt * 8 + t4 * 2;
                atomicAdd(&g_feats[r0 * 512 + col],     acc[mt][nt][0]);
                atomicAdd(&g_feats[r0 * 512 + col + 1], acc[mt][nt][1]);
                atomicAdd(&g_feats[r1 * 512 + col],     acc[mt][nt][2]);
                atomicAdd(&g_feats[r1 * 512 + col + 1], acc[mt][nt][3]);
            }
        }
    }
}

// ---------------- kernel 3: row norms + consistency ----------------
__global__ void post_kernel() {
    __shared__ float red[32];
    const int i = blockIdx.x;
    const int tid = threadIdx.x;
    const int base = i * 512;
    const int b0 = (i & 63) * 512;
    float sq = 0.0f, dsq = 0.0f;
    for (int f = tid; f < 512; f += 256) {
        float v = g_feats[base + f];
        sq += v * v;
        if (i >= 64) {
            float d = v - g_feats[b0 + f];
            dsq += d * d;
        }
    }
    float tsq = blockReduceSum(sq, red);
    float tdq = blockReduceSum(dsq, red);
    if (tid == 0) {
        g_norms[i] = sqrtf(tsq);
        if (i >= 64) atomicAdd(&g_cons, tdq);
    }
}

// ---------------- kernel 4: contrastive ----------------
__global__ void contr_kernel() {
    __shared__ float fi[512];
    __shared__ float simb[320];
    __shared__ float red[32];
    const int i = blockIdx.x;
    const int tid = threadIdx.x;
    for (int f = tid; f < 512; f += 256) fi[f] = g_feats[i * 512 + f];
    __syncthreads();
    const float inv_i = 1.0f / g_norms[i];
    const int w = tid >> 5, lane = tid & 31;
    for (int j = w; j < 320; j += 8) {
        float s = 0.0f;
        const float* fj = g_feats + j * 512;
        #pragma unroll 4
        for (int e = lane; e < 512; e += 32) s += fi[e] * fj[e];
        #pragma unroll
        for (int o = 16; o; o >>= 1) s += __shfl_down_sync(0xffffffffu, s, o);
        if (lane == 0) simb[j] = s * inv_i / g_norms[j] * 10.0f;
    }
    __syncthreads();
    float mx = -3.4e38f;
    for (int j = tid; j < 320; j += 256) mx = fmaxf(mx, simb[j]);
    mx = blockReduceMax(mx, red);
    float se = 0.0f;
    for (int j = tid; j < 320; j += 256) se += expf(simb[j] - mx);
    se = blockReduceSum(se, red);
    if (tid == 0) {
        float lse = mx + logf(se);
        float c = 0.0f;
        if (i > 0)   c += lse - simb[i - 1];
        if (i < 319) c += lse - simb[i + 1];
        atomicAdd(&g_contr, c);
    }
}

// ---------------- kernel 5: finalize ----------------
__global__ void fin_kernel(float* __restrict__ out) {
    out[0] = g_cons * (1.0f / 131072.0f) + 0.5f * (g_contr * (1.0f / 638.0f));
}

// ---------------- launch ----------------
#define VIEWS_SMEM (24576 + 6 * PLANE * 4)   /* 24576 + 104448 = 129024 */

extern "C" void kernel_launch(void* const* d_in, const int* in_sizes, int n_in,
                              void* d_out, int out_size) {
    const float* x  = (const float*)d_in[0];
    const float* W  = (const float*)d_in[1];
    const float* b  = (const float*)d_in[2];
    const float* n1 = (const float*)d_in[3];
    const float* n2 = (const float*)d_in[4];
    const int* fs   = (const int*)d_in[5];
    const int* ts   = (const int*)d_in[6];
    (void)in_sizes; (void)n_in; (void)out_size;

    cudaFuncSetAttribute(views_kernel, cudaFuncAttributeMaxDynamicSharedMemorySize, VIEWS_SMEM);
    cudaFuncSetAttribute(gemm_kernel, cudaFuncAttributeMaxDynamicSharedMemorySize, GEMM_SMEM);

    init_kernel<<<640, 256>>>(b);
    views_kernel<<<4608, 512, VIEWS_SMEM>>>(x, W, n1, n2, fs, ts);
    gemm_kernel<<<dim3(4, 5, 22), 128, GEMM_SMEM>>>();
    post_kernel<<<320, 256>>>();
    contr_kernel<<<320, 256>>>();
    fin_kernel<<<1, 1>>>((float*)d_out);
}

// round 6
// speedup vs baseline: 1.3420x; 1.3420x over previous
#include <cuda_runtime.h>
#include <cuda_bf16.h>
#include <math.h>
#include <stdint.h>

#define TT 4096
#define KTOT (64*4096)   /* 262144 */
#define FD 512

// ---------------- scratch (static device globals) ----------------
__device__ __nv_bfloat16 g_Ah[(size_t)320 * KTOT];
__device__ __nv_bfloat16 g_Al[(size_t)320 * KTOT];
__device__ __nv_bfloat16 g_Wh[(size_t)KTOT * FD];
__device__ __nv_bfloat16 g_Wl[(size_t)KTOT * FD];
__device__ float g_feats[320 * FD];
__device__ float g_norms[320];
__device__ float g_cons;
__device__ float g_contr;

// ---------------- PTX helpers (baseline ISA only) ----------------
__device__ __forceinline__ uint32_t smem_to_u32(const void* p) {
    uint32_t a;
    asm("{ .reg .u64 t; cvta.to.shared.u64 t, %1; cvt.u32.u64 %0, t; }" : "=r"(a) : "l"(p));
    return a;
}
__device__ __forceinline__ void ldsm_x4(uint32_t* r, uint32_t addr) {
    asm volatile("ldmatrix.sync.aligned.m8n8.x4.shared.b16 {%0,%1,%2,%3}, [%4];"
        : "=r"(r[0]), "=r"(r[1]), "=r"(r[2]), "=r"(r[3]) : "r"(addr));
}
__device__ __forceinline__ void ldsm_x2_trans(uint32_t* r, uint32_t addr) {
    asm volatile("ldmatrix.sync.aligned.m8n8.x2.trans.shared.b16 {%0,%1}, [%2];"
        : "=r"(r[0]), "=r"(r[1]) : "r"(addr));
}
__device__ __forceinline__ void mma_bf16(float* c, const uint32_t* a, const uint32_t* b) {
    asm volatile("mma.sync.aligned.m16n8k16.row.col.f32.bf16.bf16.f32 "
        "{%0,%1,%2,%3}, {%4,%5,%6,%7}, {%8,%9}, {%0,%1,%2,%3};"
        : "+f"(c[0]), "+f"(c[1]), "+f"(c[2]), "+f"(c[3])
        : "r"(a[0]), "r"(a[1]), "r"(a[2]), "r"(a[3]), "r"(b[0]), "r"(b[1]));
}
__device__ __forceinline__ void cp_async16(uint32_t smem, const void* g) {
    asm volatile("cp.async.cg.shared.global [%0], [%1], 16;" :: "r"(smem), "l"(g));
}
#define CP_COMMIT() asm volatile("cp.async.commit_group;" ::: "memory")
#define CP_WAIT1()  asm volatile("cp.async.wait_group 1;" ::: "memory")
#define CP_WAIT0()  asm volatile("cp.async.wait_group 0;" ::: "memory")

// ---------------- block reductions ----------------
__device__ __forceinline__ float blockReduceSum(float v, float* red) {
    int lane = threadIdx.x & 31, w = threadIdx.x >> 5;
    int nw = blockDim.x >> 5;
    #pragma unroll
    for (int o = 16; o; o >>= 1) v += __shfl_down_sync(0xffffffffu, v, o);
    if (lane == 0) red[w] = v;
    __syncthreads();
    if (w == 0) {
        float r = (lane < nw) ? red[lane] : 0.0f;
        #pragma unroll
        for (int o = 8; o; o >>= 1) r += __shfl_down_sync(0xffffffffu, r, o);
        if (lane == 0) red[0] = r;
    }
    __syncthreads();
    float out = red[0];
    __syncthreads();
    return out;
}
__device__ __forceinline__ float blockReduceMax(float v, float* red) {
    int lane = threadIdx.x & 31, w = threadIdx.x >> 5;
    int nw = blockDim.x >> 5;
    #pragma unroll
    for (int o = 16; o; o >>= 1) v = fmaxf(v, __shfl_down_sync(0xffffffffu, v, o));
    if (lane == 0) red[w] = v;
    __syncthreads();
    if (w == 0) {
        float r = (lane < nw) ? red[lane] : -3.4e38f;
        #pragma unroll
        for (int o = 8; o; o >>= 1) r = fmaxf(r, __shfl_down_sync(0xffffffffu, r, o));
        if (lane == 0) red[0] = r;
    }
    __syncthreads();
    float out = red[0];
    __syncthreads();
    return out;
}

// ---------------- complex / masks / skew ----------------
__device__ __forceinline__ float2 cmul(float2 a, float2 b) {
    return make_float2(a.x*b.x - a.y*b.y, a.x*b.y + a.y*b.x);
}
__device__ __forceinline__ float2 cmulc(float2 a, float2 b) {   // conj(a)*b
    return make_float2(a.x*b.x + a.y*b.y, a.x*b.y - a.y*b.x);
}
template<int MID>
__device__ __forceinline__ float maskval(int k, int fs) {
    float fm = (k >= fs && k < fs + 409) ? 0.1f : 1.0f;
    if (MID == 0) return (k < 2048) ? 1.0f : 0.0f;
    if (MID == 1) return fm;
    float g = (k == 0) ? 1.0f : ((k <= 1024) ? 0.5f : ((k < 3072) ? 1.0f : 0.5f));
    return g * fm;
}
__device__ __forceinline__ int skw2(int g) { return g + (g >> 2); }
#define PLANE2 5120   /* float2 slots per skewed 4096-plane */

// ---------------- kernel 0: init ----------------
__global__ void init_kernel(const float* __restrict__ b) {
    int i = blockIdx.x * blockDim.x + threadIdx.x;
    if (i < 320 * FD) g_feats[i] = b[i & 511];
    if (i == 0) { g_cons = 0.0f; g_contr = 0.0f; }
}

// ---------------- views helpers ----------------
__device__ __forceinline__ void store_hl(size_t idx, float v) {
    __nv_bfloat16 h = __float2bfloat16_rn(v);
    g_Ah[idx] = h;
    g_Al[idx] = __float2bfloat16_rn(v - __bfloat162float(h));
}

// 5 radix-4 smem stages (s2=2..10). FWD=1: forward twiddles; FWD=0: conj.
// src starts in B0; returns result pointer (== B1 after 5 swaps).
template<int FWD>
__device__ float2* fft_stages(const float2* __restrict__ tw, float2* B0, float2* B1, int tid) {
    float2 *src = B0, *dst = B1;
    #pragma unroll 1
    for (int s2 = 2; s2 < 12; s2 += 2) {
        const int m = 1 << s2;
        __syncthreads();
        #pragma unroll
        for (int i = tid; i < 1024; i += 512) {
            int jm = (i >> s2) << s2;
            float2 e0 = src[skw2(i)];
            float2 e1 = src[skw2(i + 1024)];
            float2 e2 = src[skw2(i + 2048)];
            float2 e3 = src[skw2(i + 3072)];
            float s02r = e0.x + e2.x, s02i = e0.y + e2.y;
            float d02r = e0.x - e2.x, d02i = e0.y - e2.y;
            float s13r = e1.x + e3.x, s13i = e1.y + e3.y;
            float d13r = e1.x - e3.x, d13i = e1.y - e3.y;
            int base = i + 3 * jm;
            dst[skw2(base)] = make_float2(s02r + s13r, s02i + s13i);
            float2 w1 = tw[jm], w2 = tw[2 * jm], w3 = tw[3 * jm];
            if (FWD) {
                dst[skw2(base + m)]   = cmul(w1, make_float2(d02r + d13i, d02i - d13r));
                dst[skw2(base + 2*m)] = cmul(w2, make_float2(s02r - s13r, s02i - s13i));
                dst[skw2(base + 3*m)] = cmul(w3, make_float2(d02r - d13i, d02i + d13r));
            } else {
                dst[skw2(base + m)]   = cmulc(w1, make_float2(d02r - d13i, d02i + d13r));
                dst[skw2(base + 2*m)] = cmulc(w2, make_float2(s02r - s13r, s02i - s13i));
                dst[skw2(base + 3*m)] = cmulc(w3, make_float2(d02r + d13i, d02i - d13r));
            }
        }
        float2* t = src; src = dst; dst = t;
    }
    __syncthreads();
    return src;   // 5 swaps from B0 -> B1
}

// masked inverse pass: stage0 from registers (Xr), then 5 smem stages. Result in B1.
template<int MID>
__device__ float2* inv_pass(const float2* __restrict__ tw, const float2* Xr,
                            float2* B0, float2* B1, int fs, int tid) {
    __syncthreads();
    #pragma unroll
    for (int j0 = 0; j0 < 2; j0++) {
        int i = tid + 512 * j0;
        float m0 = maskval<MID>(i, fs);
        float m1 = maskval<MID>(i + 1024, fs);
        float m2 = maskval<MID>(i + 2048, fs);
        float m3 = maskval<MID>(i + 3072, fs);
        float2 e0 = Xr[j0];     e0.x *= m0; e0.y *= m0;
        float2 e1 = Xr[j0 + 2]; e1.x *= m1; e1.y *= m1;
        float2 e2 = Xr[j0 + 4]; e2.x *= m2; e2.y *= m2;
        float2 e3 = Xr[j0 + 6]; e3.x *= m3; e3.y *= m3;
        float s02r = e0.x + e2.x, s02i = e0.y + e2.y;
        float d02r = e0.x - e2.x, d02i = e0.y - e2.y;
        float s13r = e1.x + e3.x, s13i = e1.y + e3.y;
        float d13r = e1.x - e3.x, d13i = e1.y - e3.y;
        int base = 4 * i;
        B0[skw2(base)] = make_float2(s02r + s13r, s02i + s13i);
        float2 w1 = tw[i], w2 = tw[2 * i], w3 = tw[3 * i];
        B0[skw2(base + 1)] = cmulc(w1, make_float2(d02r - d13i, d02i + d13r));
        B0[skw2(base + 2)] = cmulc(w2, make_float2(s02r - s13r, s02i - s13i));
        B0[skw2(base + 3)] = cmulc(w3, make_float2(d02r + d13i, d02i - d13r));
    }
    return fft_stages<0>(tw, B0, B1, tid);
}

// ---------------- kernel 1: fused views (FFT) + W split ----------------
__global__ void __launch_bounds__(512, 2)
views_kernel(const float* __restrict__ x, const float* __restrict__ W,
             const float* __restrict__ nz1, const float* __restrict__ nz2,
             const int* __restrict__ pfs, const int* __restrict__ pts) {
    const int bx = blockIdx.x;
    const int grp = bx / 9, rr9 = bx % 9;
    const int tid = threadIdx.x;

    if (rr9 == 0) {
        // ---- W hi/lo split slice ----
        size_t base = (size_t)grp * 262144;
        #pragma unroll 1
        for (int j = 0; j < 64; j++) {
            size_t i = base + (size_t)j * 4096 + (size_t)tid * 8;
            float4 v0 = *(const float4*)(W + i);
            float4 v1 = *(const float4*)(W + i + 4);
            __align__(16) __nv_bfloat16 hi[8], lo[8];
            float vv[8] = {v0.x, v0.y, v0.z, v0.w, v1.x, v1.y, v1.z, v1.w};
            #pragma unroll
            for (int q = 0; q < 8; q++) {
                __nv_bfloat16 h = __float2bfloat16_rn(vv[q]);
                hi[q] = h;
                lo[q] = __float2bfloat16_rn(vv[q] - __bfloat162float(h));
            }
            *(float4*)(g_Wh + i) = *(float4*)hi;
            *(float4*)(g_Wl + i) = *(float4*)lo;
        }
        return;
    }

    extern __shared__ char smraw[];
    float2* tw = (float2*)smraw;                     // 3072 float2 = 24576 B
    float2* B0 = (float2*)(smraw + 24576);           // PLANE2 float2
    float2* B1 = B0 + PLANE2;
    __shared__ float red[32];

    const int row = grp * 8 + (rr9 - 1);             // 0..4095
    const int bi = row >> 6, ci = row & 63;
    const int fs = *pfs, ts = *pts;
    const size_t xbase = (size_t)row * TT;

    const size_t a0 = (size_t)(0*64 + bi) * KTOT + (size_t)ci * TT;
    const size_t a1 = (size_t)(1*64 + bi) * KTOT + (size_t)ci * TT;
    const size_t a2 = (size_t)(2*64 + bi) * KTOT + (size_t)ci * TT;
    const size_t a3 = (size_t)(3*64 + bi) * KTOT + (size_t)ci * TT;
    const size_t a4 = (size_t)(4*64 + bi) * KTOT + (size_t)ci * TT;

    for (int k = tid; k < 3072; k += 512) {
        float s, c;
        sincospif(-(float)k * (1.0f / 2048.0f), &s, &c);
        tw[k] = make_float2(c, s);
    }

    // load x row into registers (xv[j] = x[tid + 512j]); view0 + std stats
    float xv[8];
    float ls = 0.0f, lq = 0.0f;
    #pragma unroll
    for (int j = 0; j < 8; j++) {
        int t = tid + 512 * j;
        float v = x[xbase + t];
        xv[j] = v;
        store_hl(a0 + t, v);
        ls += v; lq += v * v;
    }
    float s1 = blockReduceSum(ls, red);
    float q1 = blockReduceSum(lq, red);
    float std1 = sqrtf(fmaxf(0.0f, (q1 - s1 * s1 * (1.0f / 4096.0f)) * (1.0f / 4095.0f)));

    #pragma unroll
    for (int j = 0; j < 8; j++) {
        int t = tid + 512 * j;
        store_hl(a3 + t, xv[j] + nz1[xbase + t] * (0.02f * std1));
    }

    // ---- forward stage 0 from registers (real input) ----
    __syncthreads();   // twiddles ready
    #pragma unroll
    for (int j0 = 0; j0 < 2; j0++) {
        int i = tid + 512 * j0;
        float x0 = xv[j0], x1 = xv[j0 + 2], x2 = xv[j0 + 4], x3 = xv[j0 + 6];
        float s02 = x0 + x2, d02 = x0 - x2;
        float s13 = x1 + x3, d13 = x1 - x3;
        int base = 4 * i;
        float2 w1 = tw[i], w2 = tw[2 * i], w3 = tw[3 * i];
        B0[skw2(base)]     = make_float2(s02 + s13, 0.0f);
        B0[skw2(base + 1)] = make_float2(w1.x * d02 + w1.y * d13, -w1.x * d13 + w1.y * d02);
        float y2 = s02 - s13;
        B0[skw2(base + 2)] = make_float2(w2.x * y2, w2.y * y2);
        B0[skw2(base + 3)] = make_float2(w3.x * d02 - w3.y * d13, w3.x * d13 + w3.y * d02);
    }
    float2* Xp = fft_stages<1>(tw, B0, B1, tid);   // X in B1

    // stash X into registers
    float2 Xr[8];
    #pragma unroll
    for (int j = 0; j < 8; j++) Xr[j] = Xp[skw2(tid + 512 * j)];

    // ---- pass 0: compressed ----
    {
        float2* r = inv_pass<0>(tw, Xr, B0, B1, fs, tid);
        #pragma unroll
        for (int j = 0; j < 8; j++) {
            int t = tid + 512 * j;
            store_hl(a1 + t, r[skw2(t)].x * (1.0f / 4096.0f));
        }
    }
    // ---- pass 1: distorted ----
    {
        float2* r = inv_pass<1>(tw, Xr, B0, B1, fs, tid);
        #pragma unroll
        for (int j = 0; j < 8; j++) {
            int t = tid + 512 * j;
            float tm = (t >= ts && t < ts + 204) ? 0.1f : 1.0f;
            store_hl(a2 + t, tm * r[skw2(t)].x * (1.0f / 4096.0f));
        }
    }
    // ---- pass 2: combined ----
    {
        float2* r = inv_pass<2>(tw, Xr, B0, B1, fs, tid);
        float ls2 = 0.0f, lq2 = 0.0f;
        float vv[8];
        #pragma unroll
        for (int j = 0; j < 8; j++) {
            int t = tid + 512 * j;
            float tm = (t >= ts && t < ts + 204) ? 0.1f : 1.0f;
            float v = tm * r[skw2(t)].x * (1.0f / 4096.0f);
            vv[j] = v;
            ls2 += v; lq2 += v * v;
        }
        float s2 = blockReduceSum(ls2, red);
        float q2 = blockReduceSum(lq2, red);
        float std2 = sqrtf(fmaxf(0.0f, (q2 - s2 * s2 * (1.0f / 4096.0f)) * (1.0f / 4095.0f)));
        #pragma unroll
        for (int j = 0; j < 8; j++) {
            int t = tid + 512 * j;
            store_hl(a4 + t, vv[j] + nz2[xbase + t] * (0.02f * std2));
        }
    }
}

// ---------------- kernel 2: 3-stage async mma.sync bf16-split GEMM ----------------
// stage layout (24576 B): AH[0,4K) AL[4K,8K) WH[8K,16K) WL[16K,24K)
#define STG 24576
#define GEMM_SMEM (3 * STG)   /* 73728 */

__global__ void __launch_bounds__(128, 3) gemm_kernel() {
    extern __shared__ char smbuf[];
    const uint32_t sb = smem_to_u32(smbuf);

    const int tid = threadIdx.x;
    const int warp = tid >> 5, lane = tid & 31;
    const int m0 = blockIdx.y * 64;
    const int n0 = blockIdx.x * 128;
    const int z = blockIdx.z;
    const int start_chunk = 372 * z + (z < 8 ? z : 8);
    const int nchunks = 372 + (z < 8 ? 1 : 0);

    const int wm = warp >> 1;
    const int wn = warp & 1;

    float acc[2][8][4];
    #pragma unroll
    for (int a = 0; a < 2; a++)
        #pragma unroll
        for (int b = 0; b < 8; b++)
            #pragma unroll
            for (int c = 0; c < 4; c++) acc[a][b][c] = 0.0f;

    const __nv_bfloat16* srcA[4];
    uint32_t dstA[4];
    #pragma unroll
    for (int i = 0; i < 2; i++) {
        int f = tid + 128 * i;
        int m = f >> 2, kc = f & 3;
        uint32_t rel = (uint32_t)(m * 64 + (((kc + (m >> 1)) & 3) << 4));
        size_t src = (size_t)(m0 + m) * KTOT + (size_t)start_chunk * 32 + kc * 8;
        dstA[i] = rel;            srcA[i] = g_Ah + src;
        dstA[i + 2] = rel + 4096; srcA[i + 2] = g_Al + src;
    }
    const __nv_bfloat16* srcW[8];
    uint32_t dstW[8];
    #pragma unroll
    for (int i = 0; i < 4; i++) {
        int f = tid + 128 * i;
        int k = f >> 4, nc = f & 15;
        uint32_t rel = (uint32_t)(8192 + k * 256 + (((nc ^ (k & 7)) & 15) << 4));
        size_t src = ((size_t)start_chunk * 32 + k) * 512 + n0 + nc * 8;
        dstW[i] = rel;            srcW[i] = g_Wh + src;
        dstW[i + 4] = rel + 8192; srcW[i + 4] = g_Wl + src;
    }

    uint32_t a_ld[2][2];
    {
        int tile = lane >> 3, r = lane & 7;
        #pragma unroll
        for (int mt = 0; mt < 2; mt++)
            #pragma unroll
            for (int kt = 0; kt < 2; kt++) {
                int mm = wm * 32 + mt * 16 + (tile & 1) * 8 + r;
                int kb = kt * 2 + (tile >> 1);
                a_ld[mt][kt] = (uint32_t)(mm * 64 + (((kb + (mm >> 1)) & 3) << 4));
            }
    }
    uint32_t b_ld[8][2];
    {
        int lr = lane & 15;
        #pragma unroll
        for (int nt = 0; nt < 8; nt++) {
            int nb = wn * 8 + nt;
            #pragma unroll
            for (int kt = 0; kt < 2; kt++) {
                int k = kt * 16 + lr;
                b_ld[nt][kt] = (uint32_t)(8192 + k * 256 + (((nb ^ (k & 7)) & 15) << 4));
            }
        }
    }

    auto issue = [&](uint32_t sbase) {
        #pragma unroll
        for (int i = 0; i < 4; i++) {
            cp_async16(sb + sbase + dstA[i], srcA[i]);
            srcA[i] += 32;
        }
        #pragma unroll
        for (int i = 0; i < 8; i++) {
            cp_async16(sb + sbase + dstW[i], srcW[i]);
            srcW[i] += 32 * 512;
        }
    };

    issue(0);       CP_COMMIT();
    issue(STG);     CP_COMMIT();

    int cur = 0, nxt2 = 2 * STG;
    for (int it = 0; it < nchunks; ++it) {
        if (it + 1 < nchunks) { CP_WAIT1(); } else { CP_WAIT0(); }
        __syncthreads();
        if (it + 2 < nchunks) {
            issue((uint32_t)nxt2);
            CP_COMMIT();
            nxt2 += STG; if (nxt2 == 3 * STG) nxt2 = 0;
        }
        const uint32_t cbase = (uint32_t)cur;
        cur += STG; if (cur == 3 * STG) cur = 0;

        #pragma unroll
        for (int kt = 0; kt < 2; kt++) {
            uint32_t ah[2][4], al[2][4];
            #pragma unroll
            for (int mt = 0; mt < 2; mt++) {
                ldsm_x4(ah[mt], sb + cbase + a_ld[mt][kt]);
                ldsm_x4(al[mt], sb + cbase + a_ld[mt][kt] + 4096);
            }
            uint32_t bh[8][2], bl[8][2];
            #pragma unroll
            for (int nt = 0; nt < 8; nt++) {
                ldsm_x2_trans(bh[nt], sb + cbase + b_ld[nt][kt]);
                ldsm_x2_trans(bl[nt], sb + cbase + b_ld[nt][kt] + 8192);
            }
            #pragma unroll
            for (int mt = 0; mt < 2; mt++)
                #pragma unroll
                for (int nt = 0; nt < 8; nt++) {
                    mma_bf16(acc[mt][nt], ah[mt], bh[nt]);
                    mma_bf16(acc[mt][nt], ah[mt], bl[nt]);
                    mma_bf16(acc[mt][nt], al[mt], bh[nt]);
                }
        }
    }

    // epilogue
    {
        const int g = lane >> 2, t4 = lane & 3;
        #pragma unroll
        for (int mt = 0; mt < 2; mt++) {
            int r0 = m0 + wm * 32 + mt * 16 + g;
            int r1 = r0 + 8;
            #pragma unroll
            for (int nt = 0; nt < 8; nt++) {
                int col = n0 + wn * 64 + nt * 8 + t4 * 2;
                atomicAdd(&g_feats[r0 * 512 + col],     acc[mt][nt][0]);
                atomicAdd(&g_feats[r0 * 512 + col + 1], acc[mt][nt][1]);
                atomicAdd(&g_feats[r1 * 512 + col],     acc[mt][nt][2]);
                atomicAdd(&g_feats[r1 * 512 + col + 1], acc[mt][nt][3]);
            }
        }
    }
}

// ---------------- kernel 3: row norms + consistency ----------------
__global__ void post_kernel() {
    __shared__ float red[32];
    const int i = blockIdx.x;
    const int tid = threadIdx.x;
    const int base = i * 512;
    const int b0 = (i & 63) * 512;
    float sq = 0.0f, dsq = 0.0f;
    for (int f = tid; f < 512; f += 256) {
        float v = g_feats[base + f];
        sq += v * v;
        if (i >= 64) {
            float d = v - g_feats[b0 + f];
            dsq += d * d;
        }
    }
    float tsq = blockReduceSum(sq, red);
    float tdq = blockReduceSum(dsq, red);
    if (tid == 0) {
        g_norms[i] = sqrtf(tsq);
        if (i >= 64) atomicAdd(&g_cons, tdq);
    }
}

// ---------------- kernel 4: contrastive ----------------
__global__ void contr_kernel() {
    __shared__ float fi[512];
    __shared__ float simb[320];
    __shared__ float red[32];
    const int i = blockIdx.x;
    const int tid = threadIdx.x;
    for (int f = tid; f < 512; f += 256) fi[f] = g_feats[i * 512 + f];
    __syncthreads();
    const float inv_i = 1.0f / g_norms[i];
    const int w = tid >> 5, lane = tid & 31;
    for (int j = w; j < 320; j += 8) {
        float s = 0.0f;
        const float* fj = g_feats + j * 512;
        #pragma unroll 4
        for (int e = lane; e < 512; e += 32) s += fi[e] * fj[e];
        #pragma unroll
        for (int o = 16; o; o >>= 1) s += __shfl_down_sync(0xffffffffu, s, o);
        if (lane == 0) simb[j] = s * inv_i / g_norms[j] * 10.0f;
    }
    __syncthreads();
    float mx = -3.4e38f;
    for (int j = tid; j < 320; j += 256) mx = fmaxf(mx, simb[j]);
    mx = blockReduceMax(mx, red);
    float se = 0.0f;
    for (int j = tid; j < 320; j += 256) se += expf(simb[j] - mx);
    se = blockReduceSum(se, red);
    if (tid == 0) {
        float lse = mx + logf(se);
        float c = 0.0f;
        if (i > 0)   c += lse - simb[i - 1];
        if (i < 319) c += lse - simb[i + 1];
        atomicAdd(&g_contr, c);
    }
}

// ---------------- kernel 5: finalize ----------------
__global__ void fin_kernel(float* __restrict__ out) {
    out[0] = g_cons * (1.0f / 131072.0f) + 0.5f * (g_contr * (1.0f / 638.0f));
}

// ---------------- launch ----------------
#define VIEWS_SMEM (24576 + 2 * PLANE2 * 8)   /* 24576 + 81920 = 106496 */

extern "C" void kernel_launch(void* const* d_in, const int* in_sizes, int n_in,
                              void* d_out, int out_size) {
    const float* x  = (const float*)d_in[0];
    const float* W  = (const float*)d_in[1];
    const float* b  = (const float*)d_in[2];
    const float* n1 = (const float*)d_in[3];
    const float* n2 = (const float*)d_in[4];
    const int* fs   = (const int*)d_in[5];
    const int* ts   = (const int*)d_in[6];
    (void)in_sizes; (void)n_in; (void)out_size;

    cudaFuncSetAttribute(views_kernel, cudaFuncAttributeMaxDynamicSharedMemorySize, VIEWS_SMEM);
    cudaFuncSetAttribute(gemm_kernel, cudaFuncAttributeMaxDynamicSharedMemorySize, GEMM_SMEM);

    init_kernel<<<640, 256>>>(b);
    views_kernel<<<4608, 512, VIEWS_SMEM>>>(x, W, n1, n2, fs, ts);
    gemm_kernel<<<dim3(4, 5, 22), 128, GEMM_SMEM>>>();
    post_kernel<<<320, 256>>>();
    contr_kernel<<<320, 256>>>();
    fin_kernel<<<1, 1>>>((float*)d_out);
}

// round 7
// speedup vs baseline: 1.5237x; 1.1354x over previous
#include <cuda_runtime.h>
#include <cuda_bf16.h>
#include <math.h>
#include <stdint.h>

#define TT 4096
#define KTOT (64*4096)   /* 262144 */
#define FD 512

// ---------------- scratch (static device globals) ----------------
__device__ __nv_bfloat16 g_Ah[(size_t)320 * KTOT];
__device__ __nv_bfloat16 g_Al[(size_t)320 * KTOT];
__device__ __nv_bfloat16 g_Wh[(size_t)KTOT * FD];
__device__ __nv_bfloat16 g_Wl[(size_t)KTOT * FD];
__device__ float g_feats[320 * FD];
__device__ float g_norms[320];
__device__ float g_cons;
__device__ float g_contr;

// ---------------- PTX helpers (baseline ISA only) ----------------
__device__ __forceinline__ uint32_t smem_to_u32(const void* p) {
    uint32_t a;
    asm("{ .reg .u64 t; cvta.to.shared.u64 t, %1; cvt.u32.u64 %0, t; }" : "=r"(a) : "l"(p));
    return a;
}
__device__ __forceinline__ void ldsm_x4(uint32_t* r, uint32_t addr) {
    asm volatile("ldmatrix.sync.aligned.m8n8.x4.shared.b16 {%0,%1,%2,%3}, [%4];"
        : "=r"(r[0]), "=r"(r[1]), "=r"(r[2]), "=r"(r[3]) : "r"(addr));
}
__device__ __forceinline__ void ldsm_x4_trans(uint32_t* r, uint32_t addr) {
    asm volatile("ldmatrix.sync.aligned.m8n8.x4.trans.shared.b16 {%0,%1,%2,%3}, [%4];"
        : "=r"(r[0]), "=r"(r[1]), "=r"(r[2]), "=r"(r[3]) : "r"(addr));
}
__device__ __forceinline__ void mma_bf16(float* c, const uint32_t* a, const uint32_t* b) {
    asm volatile("mma.sync.aligned.m16n8k16.row.col.f32.bf16.bf16.f32 "
        "{%0,%1,%2,%3}, {%4,%5,%6,%7}, {%8,%9}, {%0,%1,%2,%3};"
        : "+f"(c[0]), "+f"(c[1]), "+f"(c[2]), "+f"(c[3])
        : "r"(a[0]), "r"(a[1]), "r"(a[2]), "r"(a[3]), "r"(b[0]), "r"(b[1]));
}
__device__ __forceinline__ void cp_async16(uint32_t smem, const void* g) {
    asm volatile("cp.async.cg.shared.global [%0], [%1], 16;" :: "r"(smem), "l"(g));
}
#define CP_COMMIT() asm volatile("cp.async.commit_group;" ::: "memory")
#define CP_WAIT1()  asm volatile("cp.async.wait_group 1;" ::: "memory")
#define CP_WAIT0()  asm volatile("cp.async.wait_group 0;" ::: "memory")

// ---------------- block reductions ----------------
__device__ __forceinline__ float blockReduceSum(float v, float* red) {
    int lane = threadIdx.x & 31, w = threadIdx.x >> 5;
    int nw = blockDim.x >> 5;
    #pragma unroll
    for (int o = 16; o; o >>= 1) v += __shfl_down_sync(0xffffffffu, v, o);
    if (lane == 0) red[w] = v;
    __syncthreads();
    if (w == 0) {
        float r = (lane < nw) ? red[lane] : 0.0f;
        #pragma unroll
        for (int o = 8; o; o >>= 1) r += __shfl_down_sync(0xffffffffu, r, o);
        if (lane == 0) red[0] = r;
    }
    __syncthreads();
    float out = red[0];
    __syncthreads();
    return out;
}
__device__ __forceinline__ float blockReduceMax(float v, float* red) {
    int lane = threadIdx.x & 31, w = threadIdx.x >> 5;
    int nw = blockDim.x >> 5;
    #pragma unroll
    for (int o = 16; o; o >>= 1) v = fmaxf(v, __shfl_down_sync(0xffffffffu, v, o));
    if (lane == 0) red[w] = v;
    __syncthreads();
    if (w == 0) {
        float r = (lane < nw) ? red[lane] : -3.4e38f;
        #pragma unroll
        for (int o = 8; o; o >>= 1) r = fmaxf(r, __shfl_down_sync(0xffffffffu, r, o));
        if (lane == 0) red[0] = r;
    }
    __syncthreads();
    float out = red[0];
    __syncthreads();
    return out;
}

// ---------------- complex / masks / skew ----------------
__device__ __forceinline__ float2 f2add(float2 a, float2 b) { return make_float2(a.x + b.x, a.y + b.y); }
__device__ __forceinline__ float2 f2sub(float2 a, float2 b) { return make_float2(a.x - b.x, a.y - b.y); }
__device__ __forceinline__ float2 cmul(float2 a, float2 b) {
    return make_float2(a.x*b.x - a.y*b.y, a.x*b.y + a.y*b.x);
}
__device__ __forceinline__ float2 cmulc(float2 a, float2 b) {   // conj(a)*b
    return make_float2(a.x*b.x + a.y*b.y, a.x*b.y - a.y*b.x);
}
template<int MID>
__device__ __forceinline__ float maskval(int k, int fs) {
    float fm = (k >= fs && k < fs + 409) ? 0.1f : 1.0f;
    if (MID == 0) return (k < 2048) ? 1.0f : 0.0f;
    if (MID == 1) return fm;
    float g = (k == 0) ? 1.0f : ((k <= 1024) ? 0.5f : ((k < 3072) ? 1.0f : 0.5f));
    return g * fm;
}
__device__ __forceinline__ int skw3(int g) { return g + (g >> 3); }
#define PLANE3 4608   /* float2 slots per skewed 4096-plane */

// ---------------- radix-8 butterfly (DFT-8 via two DFT-4 + omega8 combine) ----------------
template<int FWD>
__device__ __forceinline__ void dft8(const float2* e, float2* y) {
    // A = DFT4(e0,e2,e4,e6)
    float2 a02s = f2add(e[0], e[4]), a02d = f2sub(e[0], e[4]);
    float2 a13s = f2add(e[2], e[6]), a13d = f2sub(e[2], e[6]);
    float2 A0 = f2add(a02s, a13s), A2 = f2sub(a02s, a13s);
    float2 A1, A3;
    if (FWD) {
        A1 = make_float2(a02d.x + a13d.y, a02d.y - a13d.x);
        A3 = make_float2(a02d.x - a13d.y, a02d.y + a13d.x);
    } else {
        A1 = make_float2(a02d.x - a13d.y, a02d.y + a13d.x);
        A3 = make_float2(a02d.x + a13d.y, a02d.y - a13d.x);
    }
    // B = DFT4(e1,e3,e5,e7)
    float2 b02s = f2add(e[1], e[5]), b02d = f2sub(e[1], e[5]);
    float2 b13s = f2add(e[3], e[7]), b13d = f2sub(e[3], e[7]);
    float2 B0 = f2add(b02s, b13s), B2 = f2sub(b02s, b13s);
    float2 B1, B3;
    if (FWD) {
        B1 = make_float2(b02d.x + b13d.y, b02d.y - b13d.x);
        B3 = make_float2(b02d.x - b13d.y, b02d.y + b13d.x);
    } else {
        B1 = make_float2(b02d.x - b13d.y, b02d.y + b13d.x);
        B3 = make_float2(b02d.x + b13d.y, b02d.y - b13d.x);
    }
    const float c = 0.7071067811865476f;
    float2 w1, w2, w3;
    if (FWD) {
        w1 = make_float2(c * (B1.x + B1.y), c * (B1.y - B1.x));   // omega8^1 * B1
        w2 = make_float2(B2.y, -B2.x);                            // omega8^2 * B2
        w3 = make_float2(c * (B3.y - B3.x), -c * (B3.x + B3.y));  // omega8^3 * B3
    } else {
        w1 = make_float2(c * (B1.x - B1.y), c * (B1.y + B1.x));   // omega8^-1 * B1
        w2 = make_float2(-B2.y, B2.x);                            // omega8^-2 * B2
        w3 = make_float2(-c * (B3.x + B3.y), c * (B3.x - B3.y));  // omega8^-3 * B3
    }
    y[0] = f2add(A0, B0); y[4] = f2sub(A0, B0);
    y[1] = f2add(A1, w1); y[5] = f2sub(A1, w1);
    y[2] = f2add(A2, w2); y[6] = f2sub(A2, w2);
    y[3] = f2add(A3, w3); y[7] = f2sub(A3, w3);
}

// 3 radix-8 smem stages (m = 8, 64, 512). One butterfly per thread per stage.
// src starts in B0; after 3 ping-pongs result is in B1.
template<int FWD>
__device__ float2* r8_stages(const float2* __restrict__ tw, float2* B0, float2* B1, int tid) {
    float2 *src = B0, *dst = B1;
    #pragma unroll 1
    for (int s3 = 3; s3 <= 9; s3 += 3) {
        const int m = 1 << s3;
        __syncthreads();
        const int jm = (tid >> s3) << s3;
        float2 e[8], y[8];
        #pragma unroll
        for (int q = 0; q < 8; q++) e[q] = src[skw3(tid + 512 * q)];
        dft8<FWD>(e, y);
        const int base = tid + 7 * jm;
        dst[skw3(base)] = y[0];
        #pragma unroll
        for (int p = 1; p < 8; p++) {
            float2 w = tw[p * jm];
            dst[skw3(base + p * m)] = FWD ? cmul(w, y[p]) : cmulc(w, y[p]);
        }
        float2* t = src; src = dst; dst = t;
    }
    __syncthreads();
    return src;   // == B1
}

// masked inverse pass: stage0 (m=1) from registers, then 3 smem stages. Result in B1.
template<int MID>
__device__ float2* inv_pass8(const float2* __restrict__ tw, const float2* Xr,
                             float2* B0, float2* B1, int fs, int tid) {
    __syncthreads();
    float2 e[8], y[8];
    #pragma unroll
    for (int q = 0; q < 8; q++) {
        float m = maskval<MID>(tid + 512 * q, fs);
        e[q] = make_float2(Xr[q].x * m, Xr[q].y * m);
    }
    dft8<0>(e, y);
    const int base = 8 * tid;     // jm = tid, m = 1 -> base = tid + 7*tid
    B0[skw3(base)] = y[0];
    #pragma unroll
    for (int p = 1; p < 8; p++)
        B0[skw3(base + p)] = cmulc(tw[p * tid], y[p]);
    return r8_stages<0>(tw, B0, B1, tid);
}

// ---------------- kernel 0: init ----------------
__global__ void init_kernel(const float* __restrict__ b) {
    int i = blockIdx.x * blockDim.x + threadIdx.x;
    if (i < 320 * FD) g_feats[i] = b[i & 511];
    if (i == 0) { g_cons = 0.0f; g_contr = 0.0f; }
}

// ---------------- views helpers ----------------
__device__ __forceinline__ void store_hl(size_t idx, float v) {
    __nv_bfloat16 h = __float2bfloat16_rn(v);
    g_Ah[idx] = h;
    g_Al[idx] = __float2bfloat16_rn(v - __bfloat162float(h));
}

// ---------------- kernel 1: fused views (radix-8 FFT) + W split ----------------
__global__ void __launch_bounds__(512, 2)
views_kernel(const float* __restrict__ x, const float* __restrict__ W,
             const float* __restrict__ nz1, const float* __restrict__ nz2,
             const int* __restrict__ pfs, const int* __restrict__ pts) {
    const int bx = blockIdx.x;
    const int grp = bx / 9, rr9 = bx % 9;
    const int tid = threadIdx.x;

    if (rr9 == 0) {
        // ---- W hi/lo split slice ----
        size_t base = (size_t)grp * 262144;
        #pragma unroll 1
        for (int j = 0; j < 64; j++) {
            size_t i = base + (size_t)j * 4096 + (size_t)tid * 8;
            float4 v0 = *(const float4*)(W + i);
            float4 v1 = *(const float4*)(W + i + 4);
            __align__(16) __nv_bfloat16 hi[8], lo[8];
            float vv[8] = {v0.x, v0.y, v0.z, v0.w, v1.x, v1.y, v1.z, v1.w};
            #pragma unroll
            for (int q = 0; q < 8; q++) {
                __nv_bfloat16 h = __float2bfloat16_rn(vv[q]);
                hi[q] = h;
                lo[q] = __float2bfloat16_rn(vv[q] - __bfloat162float(h));
            }
            *(float4*)(g_Wh + i) = *(float4*)hi;
            *(float4*)(g_Wl + i) = *(float4*)lo;
        }
        return;
    }

    extern __shared__ char smraw[];
    float2* tw = (float2*)smraw;                       // 4096 float2 = 32768 B
    float2* B0 = (float2*)(smraw + 32768);             // PLANE3 float2
    float2* B1 = B0 + PLANE3;
    __shared__ float red[32];

    const int row = grp * 8 + (rr9 - 1);               // 0..4095
    const int bi = row >> 6, ci = row & 63;
    const int fs = *pfs, ts = *pts;
    const size_t xbase = (size_t)row * TT;

    const size_t a0 = (size_t)(0*64 + bi) * KTOT + (size_t)ci * TT;
    const size_t a1 = (size_t)(1*64 + bi) * KTOT + (size_t)ci * TT;
    const size_t a2 = (size_t)(2*64 + bi) * KTOT + (size_t)ci * TT;
    const size_t a3 = (size_t)(3*64 + bi) * KTOT + (size_t)ci * TT;
    const size_t a4 = (size_t)(4*64 + bi) * KTOT + (size_t)ci * TT;

    // twiddles: tw[k] = exp(-2*pi*i*k/4096), k < 4096
    #pragma unroll
    for (int j = 0; j < 8; j++) {
        int k = tid + 512 * j;
        float s, c;
        sincospif(-(float)k * (1.0f / 2048.0f), &s, &c);
        tw[k] = make_float2(c, s);
    }

    // load x row into registers (xv[q] = x[tid + 512q]); view0 + std stats
    float xv[8];
    float ls = 0.0f, lq = 0.0f;
    #pragma unroll
    for (int j = 0; j < 8; j++) {
        int t = tid + 512 * j;
        float v = x[xbase + t];
        xv[j] = v;
        store_hl(a0 + t, v);
        ls += v; lq += v * v;
    }
    float s1 = blockReduceSum(ls, red);
    float q1 = blockReduceSum(lq, red);
    float std1 = sqrtf(fmaxf(0.0f, (q1 - s1 * s1 * (1.0f / 4096.0f)) * (1.0f / 4095.0f)));

    #pragma unroll
    for (int j = 0; j < 8; j++) {
        int t = tid + 512 * j;
        store_hl(a3 + t, xv[j] + nz1[xbase + t] * (0.02f * std1));
    }

    // ---- forward stage 0 from registers (real input) ----
    __syncthreads();   // twiddles ready
    {
        float2 e[8], y[8];
        #pragma unroll
        for (int q = 0; q < 8; q++) e[q] = make_float2(xv[q], 0.0f);
        dft8<1>(e, y);
        const int base = 8 * tid;
        B0[skw3(base)] = y[0];
        #pragma unroll
        for (int p = 1; p < 8; p++)
            B0[skw3(base + p)] = cmul(tw[p * tid], y[p]);
    }
    float2* Xp = r8_stages<1>(tw, B0, B1, tid);   // X in B1

    // stash X into registers
    float2 Xr[8];
    #pragma unroll
    for (int j = 0; j < 8; j++) Xr[j] = Xp[skw3(tid + 512 * j)];

    // ---- pass 0: compressed ----
    {
        float2* r = inv_pass8<0>(tw, Xr, B0, B1, fs, tid);
        #pragma unroll
        for (int j = 0; j < 8; j++) {
            int t = tid + 512 * j;
            store_hl(a1 + t, r[skw3(t)].x * (1.0f / 4096.0f));
        }
    }
    // ---- pass 1: distorted ----
    {
        float2* r = inv_pass8<1>(tw, Xr, B0, B1, fs, tid);
        #pragma unroll
        for (int j = 0; j < 8; j++) {
            int t = tid + 512 * j;
            float tm = (t >= ts && t < ts + 204) ? 0.1f : 1.0f;
            store_hl(a2 + t, tm * r[skw3(t)].x * (1.0f / 4096.0f));
        }
    }
    // ---- pass 2: combined ----
    {
        float2* r = inv_pass8<2>(tw, Xr, B0, B1, fs, tid);
        float ls2 = 0.0f, lq2 = 0.0f;
        float vv[8];
        #pragma unroll
        for (int j = 0; j < 8; j++) {
            int t = tid + 512 * j;
            float tm = (t >= ts && t < ts + 204) ? 0.1f : 1.0f;
            float v = tm * r[skw3(t)].x * (1.0f / 4096.0f);
            vv[j] = v;
            ls2 += v; lq2 += v * v;
        }
        float s2 = blockReduceSum(ls2, red);
        float q2 = blockReduceSum(lq2, red);
        float std2 = sqrtf(fmaxf(0.0f, (q2 - s2 * s2 * (1.0f / 4096.0f)) * (1.0f / 4095.0f)));
        #pragma unroll
        for (int j = 0; j < 8; j++) {
            int t = tid + 512 * j;
            store_hl(a4 + t, vv[j] + nz2[xbase + t] * (0.02f * std2));
        }
    }
}

// ---------------- kernel 2: 3-stage async mma.sync bf16-split GEMM ----------------
// stage layout (24576 B): AH[0,4K) AL[4K,8K) WH[8K,16K) WL[16K,24K)
#define STG 24576
#define GEMM_SMEM (3 * STG)   /* 73728 */

__global__ void __launch_bounds__(128, 3) gemm_kernel() {
    extern __shared__ char smbuf[];
    const uint32_t sb = smem_to_u32(smbuf);

    const int tid = threadIdx.x;
    const int warp = tid >> 5, lane = tid & 31;
    const int m0 = blockIdx.y * 64;
    const int n0 = blockIdx.x * 128;
    const int z = blockIdx.z;
    const int start_chunk = 372 * z + (z < 8 ? z : 8);
    const int nchunks = 372 + (z < 8 ? 1 : 0);

    const int wm = warp >> 1;
    const int wn = warp & 1;

    float acc[2][8][4];
    #pragma unroll
    for (int a = 0; a < 2; a++)
        #pragma unroll
        for (int b = 0; b < 8; b++)
            #pragma unroll
            for (int c = 0; c < 4; c++) acc[a][b][c] = 0.0f;

    const __nv_bfloat16* srcA[4];
    uint32_t dstA[4];
    #pragma unroll
    for (int i = 0; i < 2; i++) {
        int f = tid + 128 * i;
        int m = f >> 2, kc = f & 3;
        uint32_t rel = (uint32_t)(m * 64 + (((kc + (m >> 1)) & 3) << 4));
        size_t src = (size_t)(m0 + m) * KTOT + (size_t)start_chunk * 32 + kc * 8;
        dstA[i] = rel;            srcA[i] = g_Ah + src;
        dstA[i + 2] = rel + 4096; srcA[i + 2] = g_Al + src;
    }
    const __nv_bfloat16* srcW[8];
    uint32_t dstW[8];
    #pragma unroll
    for (int i = 0; i < 4; i++) {
        int f = tid + 128 * i;
        int k = f >> 4, nc = f & 15;
        uint32_t rel = (uint32_t)(8192 + k * 256 + (((nc ^ (k & 7)) & 15) << 4));
        size_t src = ((size_t)start_chunk * 32 + k) * 512 + n0 + nc * 8;
        dstW[i] = rel;            srcW[i] = g_Wh + src;
        dstW[i + 4] = rel + 8192; srcW[i + 4] = g_Wl + src;
    }

    uint32_t a_ld[2][2];
    {
        int tile = lane >> 3, r = lane & 7;
        #pragma unroll
        for (int mt = 0; mt < 2; mt++)
            #pragma unroll
            for (int kt = 0; kt < 2; kt++) {
                int mm = wm * 32 + mt * 16 + (tile & 1) * 8 + r;
                int kb = kt * 2 + (tile >> 1);
                a_ld[mt][kt] = (uint32_t)(mm * 64 + (((kb + (mm >> 1)) & 3) << 4));
            }
    }
    // B x4.trans addresses: [ntp][kt]; lanes 0-15 -> col nb, lanes 16-31 -> col nb+1
    uint32_t b_ld4[4][2];
    {
        int lr = lane & 15, half = lane >> 4;
        #pragma unroll
        for (int ntp = 0; ntp < 4; ntp++) {
            int nb = wn * 8 + ntp * 2 + half;
            #pragma unroll
            for (int kt = 0; kt < 2; kt++) {
                int k = kt * 16 + lr;
                b_ld4[ntp][kt] = (uint32_t)(8192 + k * 256 + (((nb ^ (k & 7)) & 15) << 4));
            }
        }
    }

    auto issue = [&](uint32_t sbase) {
        #pragma unroll
        for (int i = 0; i < 4; i++) {
            cp_async16(sb + sbase + dstA[i], srcA[i]);
            srcA[i] += 32;
        }
        #pragma unroll
        for (int i = 0; i < 8; i++) {
            cp_async16(sb + sbase + dstW[i], srcW[i]);
            srcW[i] += 32 * 512;
        }
    };

    issue(0);       CP_COMMIT();
    issue(STG);     CP_COMMIT();

    int cur = 0, nxt2 = 2 * STG;
    for (int it = 0; it < nchunks; ++it) {
        if (it + 1 < nchunks) { CP_WAIT1(); } else { CP_WAIT0(); }
        __syncthreads();
        if (it + 2 < nchunks) {
            issue((uint32_t)nxt2);
            CP_COMMIT();
            nxt2 += STG; if (nxt2 == 3 * STG) nxt2 = 0;
        }
        const uint32_t cbase = (uint32_t)cur;
        cur += STG; if (cur == 3 * STG) cur = 0;

        #pragma unroll
        for (int kt = 0; kt < 2; kt++) {
            uint32_t ah[2][4], al[2][4];
            #pragma unroll
            for (int mt = 0; mt < 2; mt++) {
                ldsm_x4(ah[mt], sb + cbase + a_ld[mt][kt]);
                ldsm_x4(al[mt], sb + cbase + a_ld[mt][kt] + 4096);
            }
            uint32_t bh[16], bl[16];   // bh[nt*2 + j]
            #pragma unroll
            for (int ntp = 0; ntp < 4; ntp++) {
                ldsm_x4_trans(&bh[ntp * 4], sb + cbase + b_ld4[ntp][kt]);
                ldsm_x4_trans(&bl[ntp * 4], sb + cbase + b_ld4[ntp][kt] + 8192);
            }
            #pragma unroll
            for (int mt = 0; mt < 2; mt++)
                #pragma unroll
                for (int nt = 0; nt < 8; nt++) {
                    mma_bf16(acc[mt][nt], ah[mt], &bh[nt * 2]);
                    mma_bf16(acc[mt][nt], ah[mt], &bl[nt * 2]);
                    mma_bf16(acc[mt][nt], al[mt], &bh[nt * 2]);
                }
        }
    }

    // epilogue
    {
        const int g = lane >> 2, t4 = lane & 3;
        #pragma unroll
        for (int mt = 0; mt < 2; mt++) {
            int r0 = m0 + wm * 32 + mt * 16 + g;
            int r1 = r0 + 8;
            #pragma unroll
            for (int nt = 0; nt < 8; nt++) {
                int col = n0 + wn * 64 + nt * 8 + t4 * 2;
                atomicAdd(&g_feats[r0 * 512 + col],     acc[mt][nt][0]);
                atomicAdd(&g_feats[r0 * 512 + col + 1], acc[mt][nt][1]);
                atomicAdd(&g_feats[r1 * 512 + col],     acc[mt][nt][2]);
                atomicAdd(&g_feats[r1 * 512 + col + 1], acc[mt][nt][3]);
            }
        }
    }
}

// ---------------- kernel 3: row norms + consistency ----------------
__global__ void post_kernel() {
    __shared__ float red[32];
    const int i = blockIdx.x;
    const int tid = threadIdx.x;
    const int base = i * 512;
    const int b0 = (i & 63) * 512;
    float sq = 0.0f, dsq = 0.0f;
    for (int f = tid; f < 512; f += 256) {
        float v = g_feats[base + f];
        sq += v * v;
        if (i >= 64) {
            float d = v - g_feats[b0 + f];
            dsq += d * d;
        }
    }
    float tsq = blockReduceSum(sq, red);
    float tdq = blockReduceSum(dsq, red);
    if (tid == 0) {
        g_norms[i] = sqrtf(tsq);
        if (i >= 64) atomicAdd(&g_cons, tdq);
    }
}

// ---------------- kernel 4: contrastive ----------------
__global__ void contr_kernel() {
    __shared__ float fi[512];
    __shared__ float simb[320];
    __shared__ float red[32];
    const int i = blockIdx.x;
    const int tid = threadIdx.x;
    for (int f = tid; f < 512; f += 256) fi[f] = g_feats[i * 512 + f];
    __syncthreads();
    const float inv_i = 1.0f / g_norms[i];
    const int w = tid >> 5, lane = tid & 31;
    for (int j = w; j < 320; j += 8) {
        float s = 0.0f;
        const float* fj = g_feats + j * 512;
        #pragma unroll 4
        for (int e = lane; e < 512; e += 32) s += fi[e] * fj[e];
        #pragma unroll
        for (int o = 16; o; o >>= 1) s += __shfl_down_sync(0xffffffffu, s, o);
        if (lane == 0) simb[j] = s * inv_i / g_norms[j] * 10.0f;
    }
    __syncthreads();
    float mx = -3.4e38f;
    for (int j = tid; j < 320; j += 256) mx = fmaxf(mx, simb[j]);
    mx = blockReduceMax(mx, red);
    float se = 0.0f;
    for (int j = tid; j < 320; j += 256) se += expf(simb[j] - mx);
    se = blockReduceSum(se, red);
    if (tid == 0) {
        float lse = mx + logf(se);
        float c = 0.0f;
        if (i > 0)   c += lse - simb[i - 1];
        if (i < 319) c += lse - simb[i + 1];
        atomicAdd(&g_contr, c);
    }
}

// ---------------- kernel 5: finalize ----------------
__global__ void fin_kernel(float* __restrict__ out) {
    out[0] = g_cons * (1.0f / 131072.0f) + 0.5f * (g_contr * (1.0f / 638.0f));
}

// ---------------- launch ----------------
#define VIEWS_SMEM (32768 + 2 * PLANE3 * 8)   /* 32768 + 73728 = 106496 */

extern "C" void kernel_launch(void* const* d_in, const int* in_sizes, int n_in,
                              void* d_out, int out_size) {
    const float* x  = (const float*)d_in[0];
    const float* W  = (const float*)d_in[1];
    const float* b  = (const float*)d_in[2];
    const float* n1 = (const float*)d_in[3];
    const float* n2 = (const float*)d_in[4];
    const int* fs   = (const int*)d_in[5];
    const int* ts   = (const int*)d_in[6];
    (void)in_sizes; (void)n_in; (void)out_size;

    cudaFuncSetAttribute(views_kernel, cudaFuncAttributeMaxDynamicSharedMemorySize, VIEWS_SMEM);
    cudaFuncSetAttribute(gemm_kernel, cudaFuncAttributeMaxDynamicSharedMemorySize, GEMM_SMEM);

    init_kernel<<<640, 256>>>(b);
    views_kernel<<<4608, 512, VIEWS_SMEM>>>(x, W, n1, n2, fs, ts);
    gemm_kernel<<<dim3(4, 5, 22), 128, GEMM_SMEM>>>();
    post_kernel<<<320, 256>>>();
    contr_kernel<<<320, 256>>>();
    fin_kernel<<<1, 1>>>((float*)d_out);
}